// round 5
// baseline (speedup 1.0000x reference)
#include <cuda_runtime.h>

// SingleChannelInterpolation — fused two-pass softmax, f32x2-packed over w-pairs.
// B=32, C=128, W=128, H=128, KAPPA=10.
// Outputs: y [B,C,H] | w [B,C,H] | y_trans [B,C,H] (concatenated).
//
// log2-domain: s2 = log2(m) - alpha2*(d-t)^2,  alpha2 = softplus(kernel)*log2(e)
// transient:   s2t = 10*s2 - 9*log2(m), shifted by Mt' = 10*M + 45 (within +-45
//              of true max since log2(m) in [-9.97, 0]) -> no 2nd max pass.
// R5: transient exponential computed as e^10 * G with G = 2^(-9*log2m - 45)
//     precomputed in shared -> 1 EX2/cell instead of 2 (MUFU was binding pipe).
//     All four accumulators packed f32x2 (lo/hi partial sums over w-pair).

constexpr int B = 32, C = 128, W = 128, H = 128;
constexpr int BDIM = 128;          // 4 warps
constexpr int CH_PER_BLOCK = 4;    // one warp per (b,c) channel
constexpr int W2 = W / 2;
constexpr float LOG2E = 1.4426950408889634f;
constexpr float LN2   = 0.6931471805599453f;

typedef unsigned long long u64;

__device__ __forceinline__ float ex2(float x) {
    float y; asm("ex2.approx.ftz.f32 %0, %1;" : "=f"(y) : "f"(x)); return y;
}
__device__ __forceinline__ float lg2(float x) {
    float y; asm("lg2.approx.ftz.f32 %0, %1;" : "=f"(y) : "f"(x)); return y;
}
__device__ __forceinline__ u64 pk(float lo, float hi) {
    u64 r; asm("mov.b64 %0, {%1, %2};" : "=l"(r) : "f"(lo), "f"(hi)); return r;
}
__device__ __forceinline__ void unpk(u64 v, float& lo, float& hi) {
    asm("mov.b64 {%0, %1}, %2;" : "=f"(lo), "=f"(hi) : "l"(v));
}
__device__ __forceinline__ u64 add2(u64 a, u64 b) {
    u64 r; asm("add.rn.f32x2 %0, %1, %2;" : "=l"(r) : "l"(a), "l"(b)); return r;
}
__device__ __forceinline__ u64 mul2(u64 a, u64 b) {
    u64 r; asm("mul.rn.f32x2 %0, %1, %2;" : "=l"(r) : "l"(a), "l"(b)); return r;
}
__device__ __forceinline__ u64 fma2(u64 a, u64 b, u64 c) {
    u64 r; asm("fma.rn.f32x2 %0, %1, %2, %3;" : "=l"(r) : "l"(a), "l"(b), "l"(c)); return r;
}

__global__ __launch_bounds__(BDIM)
void interp_kernel(const float* __restrict__ x_t,
                   const float* __restrict__ d_in_,
                   const float* __restrict__ m_in,
                   const float* __restrict__ kern,
                   float* __restrict__ out)
{
    // SoA float2 shared: w-pairs load as single 64-bit LDS into aligned reg pairs.
    __shared__ float2 NA[W2];                   // {-alpha2} pairs (channel-indep)
    __shared__ float2 DD[CH_PER_BLOCK][W2];     // d pairs
    __shared__ float2 LL[CH_PER_BLOCK][W2];     // log2(m) pairs
    __shared__ float2 XX[CH_PER_BLOCK][W2];     // x pairs
    __shared__ float2 GG[CH_PER_BLOCK][W2];     // 2^(-9*log2m - 45) pairs

    const int tid = threadIdx.x;
    const int bc0 = blockIdx.x * CH_PER_BLOCK;

    // setup: negated alpha2 (accurate softplus; amortized)
    {
        float k = kern[tid];
        ((float*)NA)[tid] = -log1pf(expf(k)) * LOG2E;
    }
    #pragma unroll
    for (int ch = 0; ch < CH_PER_BLOCK; ch++) {
        int g = (bc0 + ch) * W + tid;
        float ll = lg2(m_in[g]);
        ((float*)DD[ch])[tid] = d_in_[g];
        ((float*)LL[ch])[tid] = ll;
        ((float*)XX[ch])[tid] = x_t[g];
        ((float*)GG[ch])[tid] = ex2(fmaf(-9.0f, ll, -45.0f));
    }
    __syncthreads();

    const int warp = tid >> 5;
    const int lane = tid & 31;
    const u64* __restrict__ dd_s = (const u64*)DD[warp];
    const u64* __restrict__ na_s = (const u64*)NA;
    const u64* __restrict__ ll_s = (const u64*)LL[warp];
    const u64* __restrict__ xx_s = (const u64*)XX[warp];
    const u64* __restrict__ gg_s = (const u64*)GG[warp];

    // per-lane h targets: h = lane + 32*j, t = h * 128/127 (linspace(0,128,128))
    u64 nt2[4];
    float M[4];
    #pragma unroll
    for (int j = 0; j < 4; j++) {
        float t = (float)(lane + 32 * j) * (128.0f / 127.0f);
        nt2[j] = pk(-t, -t);
        M[j] = -1e30f;
    }

    // ---- Pass 1: M[j] = max_w s2
    #pragma unroll 4
    for (int k = 0; k < W2; k++) {
        u64 dd = dd_s[k];
        u64 na = na_s[k];
        u64 ll = ll_s[k];
        #pragma unroll
        for (int j = 0; j < 4; j++) {
            u64 diff = add2(dd, nt2[j]);
            u64 v    = mul2(diff, diff);
            u64 s2   = fma2(na, v, ll);     // log2m - a2*(d-t)^2
            float a, b; unpk(s2, a, b);
            M[j] = fmaxf(M[j], fmaxf(a, b));
        }
    }

    u64 nM2[4];
    #pragma unroll
    for (int j = 0; j < 4; j++) nM2[j] = pk(-M[j], -M[j]);

    // ---- Pass 2: softmax-weighted sums, transient via e^10 * G (no 2nd EX2)
    u64 S2[4], Y2[4], St2[4], Yt2[4];
    #pragma unroll
    for (int j = 0; j < 4; j++) { S2[j] = 0; Y2[j] = 0; St2[j] = 0; Yt2[j] = 0; }

    #pragma unroll 2
    for (int k = 0; k < W2; k++) {
        u64 dd = dd_s[k];
        u64 na = na_s[k];
        u64 ll = ll_s[k];
        u64 xx = xx_s[k];
        u64 gg = gg_s[k];
        #pragma unroll
        for (int j = 0; j < 4; j++) {
            u64 diff = add2(dd, nt2[j]);
            u64 v    = mul2(diff, diff);
            u64 s2   = fma2(na, v, ll);
            u64 sM   = add2(s2, nM2[j]);          // s2 - M  (<= 0)
            float a, b; unpk(sM, a, b);
            float e0 = ex2(a), e1 = ex2(b);
            u64 e2  = pk(e0, e1);
            u64 p2  = mul2(e2, e2);
            u64 p4  = mul2(p2, p2);
            u64 p8  = mul2(p4, p4);
            u64 p10 = mul2(p8, p2);               // e^10
            u64 et2 = mul2(p10, gg);              // 2^(s2t - (10M+45))
            S2[j]  = add2(S2[j],  e2);
            Y2[j]  = fma2(e2,  xx, Y2[j]);
            St2[j] = add2(St2[j], et2);
            Yt2[j] = fma2(et2, xx, Yt2[j]);
        }
    }

    // ---- Epilogue: combine packed halves, write y, logsumexp, y_trans
    const int bc = bc0 + warp;
    #pragma unroll
    for (int j = 0; j < 4; j++) {
        float s0, s1, y0, y1, st0, st1, yt0, yt1;
        unpk(S2[j],  s0,  s1);
        unpk(Y2[j],  y0,  y1);
        unpk(St2[j], st0, st1);
        unpk(Yt2[j], yt0, yt1);
        float S  = s0 + s1,  Y  = y0 + y1;
        float St = st0 + st1, Yt = yt0 + yt1;
        int h = lane + 32 * j;
        int o = bc * H + h;
        out[o]           = __fdividef(Y, S);
        out[B*C*H + o]   = LN2 * (M[j] + lg2(S));
        out[2*B*C*H + o] = __fdividef(Yt, St);
    }
}

extern "C" void kernel_launch(void* const* d_in, const int* in_sizes, int n_in,
                              void* d_out, int out_size)
{
    const float* x_t  = (const float*)d_in[0];
    const float* d    = (const float*)d_in[1];
    const float* m    = (const float*)d_in[2];
    const float* kern = (const float*)d_in[3];
    float* out = (float*)d_out;

    interp_kernel<<<(B * C) / CH_PER_BLOCK, BDIM>>>(x_t, d, m, kern, out);
}

// round 8
// speedup vs baseline: 1.0402x; 1.0402x over previous
#include <cuda_runtime.h>

// SingleChannelInterpolation — fused two-pass softmax, f32x2-packed over w-pairs.
// B=32, C=128, W=128, H=128, KAPPA=10.
// Outputs: y [B,C,H] | w [B,C,H] | y_trans [B,C,H] (concatenated).
//
// log2-domain: s2 = log2(m) - alpha2*(d-t)^2,  alpha2 = softplus(kernel)*log2(e)
// transient:   s2t = 10*s2 - 9*log2(m), shifted by Mt' = 10*M + 45 (within +-45
//              of true max since log2(m) in [-9.97, 0]) -> no 2nd max pass.
// Transient exponential = e^10 * G, G = 2^(-9*log2m - 45) precomputed in shared
//   -> 1 EX2/cell (MUFU floor halved vs two-EX2 version).
// R6: 8 warps/block, 2 h-groups per warp (was 4) -> 2x warps, ~-20 regs,
//     doubles latency-hiding for the EX2 -> mul-chain dependency.

constexpr int B = 32, C = 128, W = 128, H = 128;
constexpr int BDIM = 256;          // 8 warps
constexpr int CH_PER_BLOCK = 4;    // 2 warps per (b,c) channel
constexpr int JN = 2;              // h-groups per warp
constexpr int W2 = W / 2;
constexpr float LOG2E = 1.4426950408889634f;
constexpr float LN2   = 0.6931471805599453f;

typedef unsigned long long u64;

__device__ __forceinline__ float ex2(float x) {
    float y; asm("ex2.approx.ftz.f32 %0, %1;" : "=f"(y) : "f"(x)); return y;
}
__device__ __forceinline__ float lg2(float x) {
    float y; asm("lg2.approx.ftz.f32 %0, %1;" : "=f"(y) : "f"(x)); return y;
}
__device__ __forceinline__ u64 pk(float lo, float hi) {
    u64 r; asm("mov.b64 %0, {%1, %2};" : "=l"(r) : "f"(lo), "f"(hi)); return r;
}
__device__ __forceinline__ void unpk(u64 v, float& lo, float& hi) {
    asm("mov.b64 {%0, %1}, %2;" : "=f"(lo), "=f"(hi) : "l"(v));
}
__device__ __forceinline__ u64 add2(u64 a, u64 b) {
    u64 r; asm("add.rn.f32x2 %0, %1, %2;" : "=l"(r) : "l"(a), "l"(b)); return r;
}
__device__ __forceinline__ u64 mul2(u64 a, u64 b) {
    u64 r; asm("mul.rn.f32x2 %0, %1, %2;" : "=l"(r) : "l"(a), "l"(b)); return r;
}
__device__ __forceinline__ u64 fma2(u64 a, u64 b, u64 c) {
    u64 r; asm("fma.rn.f32x2 %0, %1, %2, %3;" : "=l"(r) : "l"(a), "l"(b), "l"(c)); return r;
}

__global__ __launch_bounds__(BDIM)
void interp_kernel(const float* __restrict__ x_t,
                   const float* __restrict__ d_in_,
                   const float* __restrict__ m_in,
                   const float* __restrict__ kern,
                   float* __restrict__ out)
{
    // SoA float2 shared: w-pairs load as single 64-bit LDS into aligned reg pairs.
    __shared__ float2 NA[W2];                   // {-alpha2} pairs (channel-indep)
    __shared__ float2 DD[CH_PER_BLOCK][W2];     // d pairs
    __shared__ float2 LL[CH_PER_BLOCK][W2];     // log2(m) pairs
    __shared__ float2 XX[CH_PER_BLOCK][W2];     // x pairs
    __shared__ float2 GG[CH_PER_BLOCK][W2];     // 2^(-9*log2m - 45) pairs

    const int tid = threadIdx.x;
    const int bc0 = blockIdx.x * CH_PER_BLOCK;

    // setup: negated alpha2 (accurate softplus; amortized)
    if (tid < W) {
        float k = kern[tid];
        ((float*)NA)[tid] = -log1pf(expf(k)) * LOG2E;
    }
    // fill per-channel data: 4 channels x 128 = 512 elements over 256 threads
    #pragma unroll
    for (int idx = tid; idx < CH_PER_BLOCK * W; idx += BDIM) {
        int ch = idx >> 7;
        int p  = idx & 127;
        int g  = (bc0 + ch) * W + p;
        float ll = lg2(m_in[g]);
        ((float*)DD[ch])[p] = d_in_[g];
        ((float*)LL[ch])[p] = ll;
        ((float*)XX[ch])[p] = x_t[g];
        ((float*)GG[ch])[p] = ex2(fmaf(-9.0f, ll, -45.0f));
    }
    __syncthreads();

    const int warp = tid >> 5;
    const int lane = tid & 31;
    const int ch   = warp >> 1;       // channel within block
    const int sub  = warp & 1;        // which h-half this warp owns
    const u64* __restrict__ dd_s = (const u64*)DD[ch];
    const u64* __restrict__ na_s = (const u64*)NA;
    const u64* __restrict__ ll_s = (const u64*)LL[ch];
    const u64* __restrict__ xx_s = (const u64*)XX[ch];
    const u64* __restrict__ gg_s = (const u64*)GG[ch];

    // per-lane h targets: h = lane + 32*(2*sub + j), t = h * 128/127
    u64 nt2[JN];
    float M[JN];
    #pragma unroll
    for (int j = 0; j < JN; j++) {
        float t = (float)(lane + 32 * (2 * sub + j)) * (128.0f / 127.0f);
        nt2[j] = pk(-t, -t);
        M[j] = -1e30f;
    }

    // ---- Pass 1: M[j] = max_w s2
    #pragma unroll 4
    for (int k = 0; k < W2; k++) {
        u64 dd = dd_s[k];
        u64 na = na_s[k];
        u64 ll = ll_s[k];
        #pragma unroll
        for (int j = 0; j < JN; j++) {
            u64 diff = add2(dd, nt2[j]);
            u64 v    = mul2(diff, diff);
            u64 s2   = fma2(na, v, ll);     // log2m - a2*(d-t)^2
            float a, b; unpk(s2, a, b);
            M[j] = fmaxf(M[j], fmaxf(a, b));
        }
    }

    u64 nM2[JN];
    #pragma unroll
    for (int j = 0; j < JN; j++) nM2[j] = pk(-M[j], -M[j]);

    // ---- Pass 2: softmax-weighted sums, transient via e^10 * G (1 EX2/cell)
    u64 S2[JN], Y2[JN], St2[JN], Yt2[JN];
    #pragma unroll
    for (int j = 0; j < JN; j++) { S2[j] = 0; Y2[j] = 0; St2[j] = 0; Yt2[j] = 0; }

    #pragma unroll 2
    for (int k = 0; k < W2; k++) {
        u64 dd = dd_s[k];
        u64 na = na_s[k];
        u64 ll = ll_s[k];
        u64 xx = xx_s[k];
        u64 gg = gg_s[k];
        #pragma unroll
        for (int j = 0; j < JN; j++) {
            u64 diff = add2(dd, nt2[j]);
            u64 v    = mul2(diff, diff);
            u64 s2   = fma2(na, v, ll);
            u64 sM   = add2(s2, nM2[j]);          // s2 - M  (<= 0)
            float a, b; unpk(sM, a, b);
            float e0 = ex2(a), e1 = ex2(b);
            u64 e2  = pk(e0, e1);
            u64 p2  = mul2(e2, e2);
            u64 p4  = mul2(p2, p2);
            u64 p8  = mul2(p4, p4);
            u64 p10 = mul2(p8, p2);               // e^10
            u64 et2 = mul2(p10, gg);              // 2^(s2t - (10M+45))
            S2[j]  = add2(S2[j],  e2);
            Y2[j]  = fma2(e2,  xx, Y2[j]);
            St2[j] = add2(St2[j], et2);
            Yt2[j] = fma2(et2, xx, Yt2[j]);
        }
    }

    // ---- Epilogue: combine packed halves, write y, logsumexp, y_trans
    const int bc = bc0 + ch;
    #pragma unroll
    for (int j = 0; j < JN; j++) {
        float s0, s1, y0, y1, st0, st1, yt0, yt1;
        unpk(S2[j],  s0,  s1);
        unpk(Y2[j],  y0,  y1);
        unpk(St2[j], st0, st1);
        unpk(Yt2[j], yt0, yt1);
        float S  = s0 + s1,   Y  = y0 + y1;
        float St = st0 + st1, Yt = yt0 + yt1;
        int h = lane + 32 * (2 * sub + j);
        int o = bc * H + h;
        out[o]           = __fdividef(Y, S);
        out[B*C*H + o]   = LN2 * (M[j] + lg2(S));
        out[2*B*C*H + o] = __fdividef(Yt, St);
    }
}

extern "C" void kernel_launch(void* const* d_in, const int* in_sizes, int n_in,
                              void* d_out, int out_size)
{
    const float* x_t  = (const float*)d_in[0];
    const float* d    = (const float*)d_in[1];
    const float* m    = (const float*)d_in[2];
    const float* kern = (const float*)d_in[3];
    float* out = (float*)d_out;

    interp_kernel<<<(B * C) / CH_PER_BLOCK, BDIM>>>(x_t, d, m, kern, out);
}

// round 12
// speedup vs baseline: 1.2183x; 1.1712x over previous
#include <cuda_runtime.h>

// SingleChannelInterpolation — fused softmax interpolation, f32x2-packed.
// B=32, C=128, W=128, H=128, KAPPA=10.
// Outputs: y [B,C,H] | w [B,C,H] | y_trans [B,C,H] (concatenated).
//
// log2 domain: s2 = log2(m) - a2*(d-t)^2, a2 = softplus(kernel)*log2(e).
// Shift trick: M~ = max_w(-a2*(d-t)^2) (ll-free) is a valid softmax shift:
//   s2 <= M~ (log2 m <= 0), M~ - true_max <= 10 -> e in (0,1], S >= 2^-10.
//   Transient: sMt = s2t - 10*M~ = 10*sM - 9*ll exactly; sMt <= 0 since
//   Mt <= 10*M~. logsumexp is shift-invariant -> 'w' output exact.
// R8/R12: w-split (2 warps/channel x 32 pairs, JN=4 h-groups each) for
//   occupancy with 4x LDS amortization; LDS.128 float4 shared layout.
//   Pass-1 packed max emulated (no max.f32x2 in PTX): packed nq compute,
//   then two independent scalar FMNMX chains per j, merged at the end.

constexpr int B = 32, C = 128, W = 128, H = 128;
constexpr int BDIM = 128;          // 4 warps
constexpr int CH = 2;              // channels per block; warp = (ch, w-half)
constexpr int W2 = W / 2;          // 64 w-pairs
constexpr int HALF = W2 / 2;       // 32 pairs per warp
constexpr int JN = 4;              // h-groups per warp (all 128 h)
constexpr float LOG2E = 1.4426950408889634f;
constexpr float LN2   = 0.6931471805599453f;

typedef unsigned long long u64;

__device__ __forceinline__ float ex2(float x) {
    float y; asm("ex2.approx.ftz.f32 %0, %1;" : "=f"(y) : "f"(x)); return y;
}
__device__ __forceinline__ float lg2(float x) {
    float y; asm("lg2.approx.ftz.f32 %0, %1;" : "=f"(y) : "f"(x)); return y;
}
__device__ __forceinline__ u64 pk(float lo, float hi) {
    u64 r; asm("mov.b64 %0, {%1, %2};" : "=l"(r) : "f"(lo), "f"(hi)); return r;
}
__device__ __forceinline__ void unpk(u64 v, float& lo, float& hi) {
    asm("mov.b64 {%0, %1}, %2;" : "=f"(lo), "=f"(hi) : "l"(v));
}
__device__ __forceinline__ u64 add2(u64 a, u64 b) {
    u64 r; asm("add.rn.f32x2 %0, %1, %2;" : "=l"(r) : "l"(a), "l"(b)); return r;
}
__device__ __forceinline__ u64 mul2(u64 a, u64 b) {
    u64 r; asm("mul.rn.f32x2 %0, %1, %2;" : "=l"(r) : "l"(a), "l"(b)); return r;
}
__device__ __forceinline__ u64 fma2(u64 a, u64 b, u64 c) {
    u64 r; asm("fma.rn.f32x2 %0, %1, %2, %3;" : "=l"(r) : "l"(a), "l"(b), "l"(c)); return r;
}

__global__ __launch_bounds__(BDIM)
void interp_kernel(const float* __restrict__ x_t,
                   const float* __restrict__ d_in_,
                   const float* __restrict__ m_in,
                   const float* __restrict__ kern,
                   float* __restrict__ out)
{
    __shared__ float4 DN[CH][W2];        // (d0, d1, na0, na1)   na = -alpha2
    __shared__ float4 LX[CH][W2];        // (ll0, ll1, x0, x1)   ll = log2(m)
    __shared__ float  MSH[CH][2][H];     // per-half nqmax exchange
    __shared__ float4 ACC[CH][H];        // half-1 partial (S, Y, St, Yt)

    const int tid = threadIdx.x;
    const int bc0 = blockIdx.x * CH;

    // ---- setup: CH*W = 256 elements over 128 threads
    #pragma unroll
    for (int idx = tid; idx < CH * W; idx += BDIM) {
        int ch = idx >> 7;
        int p  = idx & 127;
        int g  = (bc0 + ch) * W + p;
        int pr = p >> 1, sl = p & 1;
        float na = -log1pf(expf(kern[p])) * LOG2E;
        float ll = lg2(m_in[g]);
        ((float*)&DN[ch][pr])[sl]     = d_in_[g];
        ((float*)&DN[ch][pr])[2 + sl] = na;
        ((float*)&LX[ch][pr])[sl]     = ll;
        ((float*)&LX[ch][pr])[2 + sl] = x_t[g];
    }
    __syncthreads();

    const int warp = tid >> 5;
    const int lane = tid & 31;
    const int ch   = warp >> 1;
    const int half = warp & 1;
    const int k0   = half * HALF;
    const u64* __restrict__ dn64 = (const u64*)DN[ch];
    const u64* __restrict__ lx64 = (const u64*)LX[ch];

    // per-lane h targets: h = lane + 32*j, t = h * 128/127 (linspace(0,128,128))
    u64 nt2[JN];
    float Ma[JN], Mb[JN];
    #pragma unroll
    for (int j = 0; j < JN; j++) {
        float t = (float)(lane + 32 * j) * (128.0f / 127.0f);
        nt2[j] = pk(-t, -t);
        Ma[j] = -1e30f;
        Mb[j] = -1e30f;
    }

    // ---- Pass 1 (half of w): nqmax[j] = max_w ( -a2*(d-t)^2 )
    // packed compute + two independent scalar FMNMX chains per j
    #pragma unroll 4
    for (int k = k0; k < k0 + HALF; k++) {
        u64 dd = dn64[2 * k];
        u64 nn = dn64[2 * k + 1];
        #pragma unroll
        for (int j = 0; j < JN; j++) {
            u64 diff = add2(dd, nt2[j]);
            u64 v    = mul2(diff, diff);
            u64 nq   = mul2(nn, v);
            float a, b; unpk(nq, a, b);
            Ma[j] = fmaxf(Ma[j], a);
            Mb[j] = fmaxf(Mb[j], b);
        }
    }
    // exchange halves -> global shift M~ = nqmax over all w
    #pragma unroll
    for (int j = 0; j < JN; j++)
        MSH[ch][half][32 * j + lane] = fmaxf(Ma[j], Mb[j]);
    __syncthreads();
    float Mg[JN];
    u64 nM2[JN];
    #pragma unroll
    for (int j = 0; j < JN; j++) {
        float mine  = MSH[ch][half][32 * j + lane];
        float other = MSH[ch][half ^ 1][32 * j + lane];
        Mg[j] = fmaxf(mine, other);
        nM2[j] = pk(-Mg[j], -Mg[j]);
    }

    const u64 ten2 = pk(10.0f, 10.0f);
    const u64 n9   = pk(-9.0f, -9.0f);

    // ---- Pass 2 (half of w): both softmax sums; sMt = 10*sM - 9*ll
    float S[JN]  = {0,0,0,0}, Y[JN]  = {0,0,0,0};
    float St[JN] = {0,0,0,0}, Yt[JN] = {0,0,0,0};
    #pragma unroll 2
    for (int k = k0; k < k0 + HALF; k++) {
        u64 dd = dn64[2 * k];
        u64 nn = dn64[2 * k + 1];
        u64 ll = lx64[2 * k];
        u64 xx = lx64[2 * k + 1];
        u64 rr = mul2(n9, ll);               // -9*ll (amortized over 4 j)
        float x0, x1; unpk(xx, x0, x1);
        #pragma unroll
        for (int j = 0; j < JN; j++) {
            u64 diff = add2(dd, nt2[j]);
            u64 v    = mul2(diff, diff);
            u64 s2   = fma2(nn, v, ll);      // ll - a2*(d-t)^2
            u64 sM   = add2(s2, nM2[j]);     // s2 - M~  (<= 0)
            u64 sMt  = fma2(ten2, sM, rr);   // 10*sM - 9*ll = s2t - 10*M~
            float a, b; unpk(sM,  a, b);
            float c, e; unpk(sMt, c, e);
            float e0 = ex2(a), e1 = ex2(b);
            float f0 = ex2(c), f1 = ex2(e);
            S[j]  += e0;                  S[j]  += e1;
            Y[j]   = fmaf(e0, x0, Y[j]);  Y[j]   = fmaf(e1, x1, Y[j]);
            St[j] += f0;                  St[j] += f1;
            Yt[j]  = fmaf(f0, x0, Yt[j]); Yt[j]  = fmaf(f1, x1, Yt[j]);
        }
    }

    // ---- Combine halves + epilogue (half 0 writes)
    if (half == 1) {
        #pragma unroll
        for (int j = 0; j < JN; j++)
            ACC[ch][32 * j + lane] = make_float4(S[j], Y[j], St[j], Yt[j]);
    }
    __syncthreads();
    if (half == 0) {
        const int bc = bc0 + ch;
        #pragma unroll
        for (int j = 0; j < JN; j++) {
            float4 o = ACC[ch][32 * j + lane];
            float Sg  = S[j]  + o.x;
            float Yg  = Y[j]  + o.y;
            float Stg = St[j] + o.z;
            float Ytg = Yt[j] + o.w;
            int h = lane + 32 * j;
            int q = bc * H + h;
            out[q]             = __fdividef(Yg, Sg);
            out[B*C*H + q]     = LN2 * (Mg[j] + lg2(Sg));
            out[2*B*C*H + q]   = __fdividef(Ytg, Stg);
        }
    }
}

extern "C" void kernel_launch(void* const* d_in, const int* in_sizes, int n_in,
                              void* d_out, int out_size)
{
    const float* x_t  = (const float*)d_in[0];
    const float* d    = (const float*)d_in[1];
    const float* m    = (const float*)d_in[2];
    const float* kern = (const float*)d_in[3];
    float* out = (float*)d_out;

    interp_kernel<<<(B * C) / CH, BDIM>>>(x_t, d, m, kern, out);
}